// round 7
// baseline (speedup 1.0000x reference)
#include <cuda_runtime.h>
#include <math.h>

// B=4, N=2048, M=64, L=64
// out[b,n,l] = sigmoid( (kr[l]*r[b,n,l]+br[l]) * (kl[l]*S1[l] + bl[l]*S0) )
//   S1[l] = sum_m lig[b,n,m,l]*a[b,n,m],  S0 = sum_m a[b,n,m]
//
// TWO warps per (b,n) pair (m split 32/32), doubling total warps to 16384 so
// the grid can sustain full 64-warp/SM occupancy (previous version's 8192
// warps capped occupancy at ~81% and left DRAM latency exposed).
//   warp mwarp in {0,1}: m in [mwarp*32, mwarp*32+32)
//   lane = q + 16*mh: q = L-quad (float4), mh = 16-m half within the warp
// Reduce: shfl_xor(16) within warp, then smem exchange between the 2 warps.

#define PAIRS_PER_BLOCK 4
#define THREADS 256            // 8 warps = 2 per pair
#define NUM_PAIRS (4 * 2048)

__global__ __launch_bounds__(THREADS)
void single_lr_gat_kernel(const float* __restrict__ r,
                          const float* __restrict__ lig,
                          const float* __restrict__ a,
                          const float* __restrict__ kl,
                          const float* __restrict__ bl,
                          const float* __restrict__ kr,
                          const float* __restrict__ br,
                          float* __restrict__ out) {
    const int lane  = threadIdx.x & 31;
    const int q     = lane & 15;          // quad along L
    const int mh    = lane >> 4;          // 16-m half within warp
    const int w     = threadIdx.x >> 5;   // warp in block
    const int ps    = w >> 1;             // pair slot in block
    const int mwarp = w & 1;              // which 32-m half
    const int pair  = blockIdx.x * PAIRS_PER_BLOCK + ps;

    __shared__ float a_sh[PAIRS_PER_BLOCK][64];
    __shared__ float4 s1_sh[PAIRS_PER_BLOCK][16];
    __shared__ float  s0_sh[PAIRS_PER_BLOCK];

    // Each warp stages its own 32 a-values (one float per lane, coalesced).
    a_sh[ps][mwarp * 32 + lane] = a[(size_t)pair * 64 + mwarp * 32 + lane];
    __syncwarp();

    // Each lane streams 16 float4s: m in [mwarp*32 + mh*16, +16), quad q fixed.
    const float4* __restrict__ lig4 =
        reinterpret_cast<const float4*>(lig + (size_t)pair * 64 * 64)
        + (mwarp * 32 + mh * 16) * 16 + q;
    const float* __restrict__ arow = &a_sh[ps][mwarp * 32 + mh * 16];

    float4 s1 = make_float4(0.f, 0.f, 0.f, 0.f);
    float s0 = 0.f;

#pragma unroll 8
    for (int j = 0; j < 16; ++j) {
        const float4 v = lig4[j * 16];
        const float am = arow[j];
        s1.x = fmaf(v.x, am, s1.x);
        s1.y = fmaf(v.y, am, s1.y);
        s1.z = fmaf(v.z, am, s1.z);
        s1.w = fmaf(v.w, am, s1.w);
        s0 += am;
    }

    // Intra-warp combine across the two 16-m halves.
    s1.x += __shfl_xor_sync(0xFFFFFFFF, s1.x, 16);
    s1.y += __shfl_xor_sync(0xFFFFFFFF, s1.y, 16);
    s1.z += __shfl_xor_sync(0xFFFFFFFF, s1.z, 16);
    s1.w += __shfl_xor_sync(0xFFFFFFFF, s1.w, 16);
    s0   += __shfl_xor_sync(0xFFFFFFFF, s0,   16);

    // Cross-warp combine: warp 1 publishes, warp 0 consumes + epilogue.
    if (mwarp == 1 && lane < 16) {
        s1_sh[ps][q] = s1;
        if (lane == 0) s0_sh[ps] = s0;
    }
    __syncthreads();

    if (mwarp == 0 && lane < 16) {
        const float4 t = s1_sh[ps][q];
        s1.x += t.x; s1.y += t.y; s1.z += t.z; s1.w += t.w;
        s0 += s0_sh[ps];

        const float4 kl4 = reinterpret_cast<const float4*>(kl)[q];
        const float4 bl4 = reinterpret_cast<const float4*>(bl)[q];
        const float4 kr4 = reinterpret_cast<const float4*>(kr)[q];
        const float4 br4 = reinterpret_cast<const float4*>(br)[q];
        const float4 rv  = reinterpret_cast<const float4*>(r + (size_t)pair * 64)[q];

        float4 wv;
        wv.x = fmaf(kr4.x, rv.x, br4.x) * fmaf(kl4.x, s1.x, bl4.x * s0);
        wv.y = fmaf(kr4.y, rv.y, br4.y) * fmaf(kl4.y, s1.y, bl4.y * s0);
        wv.z = fmaf(kr4.z, rv.z, br4.z) * fmaf(kl4.z, s1.z, bl4.z * s0);
        wv.w = fmaf(kr4.w, rv.w, br4.w) * fmaf(kl4.w, s1.w, bl4.w * s0);

        float4 o;
        o.x = 1.f / (1.f + expf(-wv.x));
        o.y = 1.f / (1.f + expf(-wv.y));
        o.z = 1.f / (1.f + expf(-wv.z));
        o.w = 1.f / (1.f + expf(-wv.w));

        reinterpret_cast<float4*>(out + (size_t)pair * 64)[q] = o;
    }
}

extern "C" void kernel_launch(void* const* d_in, const int* in_sizes, int n_in,
                              void* d_out, int out_size) {
    const float* r   = (const float*)d_in[0];
    const float* lig = (const float*)d_in[1];
    const float* a   = (const float*)d_in[2];
    const float* kl  = (const float*)d_in[3];
    const float* bl  = (const float*)d_in[4];
    const float* kr  = (const float*)d_in[5];
    const float* br  = (const float*)d_in[6];
    float* out = (float*)d_out;

    const int grid = NUM_PAIRS / PAIRS_PER_BLOCK;   // 8192/4 = 2048 blocks
    single_lr_gat_kernel<<<grid, THREADS>>>(r, lig, a, kl, bl, kr, br, out);
}

// round 8
// speedup vs baseline: 1.0181x; 1.0181x over previous
#include <cuda_runtime.h>
#include <math.h>

// B=4, N=2048, M=64, L=64
// out[b,n,l] = sigmoid( (kr[l]*r[b,n,l]+br[l]) * (kl[l]*S1[l] + bl[l]*S0) )
//   S1[l] = sum_m lig[b,n,m,l]*a[b,n,m],  S0 = sum_m a[b,n,m]
//
// TMA (cp.async.bulk) double-buffered pipeline:
//  - CTA = 256 threads, handles 16 consecutive pairs (grid 512 = 8192 pairs).
//  - thread 0 bulk-copies pair tile (16KB lig + 256B a) into smem ring (2 bufs),
//    mbarrier complete_tx per buffer.
//  - 8 warps compute from smem: warp w covers m-rows [8w, 8w+8);
//    lane = q + 16*mh -> quad q along L, mh picks 4 of the 8 rows.
//    shfl_xor(16) combine, cross-warp tree via smem (double-buffered),
//    warp 0 does the epilogue + store.
// In-flight DRAM bytes per SM ~ 2 bufs x 16KB x ~3.5 CTAs = ~110KB >> the
// ~12.6KB needed to cover DRAM latency at the per-SM bandwidth share.

#define THREADS 256
#define PAIRS_PER_CTA 16
#define NUM_PAIRS (4 * 2048)
#define TILE_BYTES 16384      // 64*64*4
#define A_BYTES 256           // 64*4

__device__ __forceinline__ unsigned smem_u32(const void* p) {
    return (unsigned)__cvta_generic_to_shared(p);
}

__device__ __forceinline__ void mbar_init(unsigned bar, unsigned count) {
    asm volatile("mbarrier.init.shared.b64 [%0], %1;" :: "r"(bar), "r"(count) : "memory");
}
__device__ __forceinline__ void mbar_expect_tx(unsigned bar, unsigned bytes) {
    asm volatile("mbarrier.arrive.expect_tx.shared.b64 _, [%0], %1;"
                 :: "r"(bar), "r"(bytes) : "memory");
}
__device__ __forceinline__ void bulk_g2s(unsigned dst, const void* src, unsigned bytes, unsigned bar) {
    asm volatile("cp.async.bulk.shared::cta.global.mbarrier::complete_tx::bytes "
                 "[%0], [%1], %2, [%3];"
                 :: "r"(dst), "l"(src), "r"(bytes), "r"(bar) : "memory");
}
__device__ __forceinline__ void mbar_wait(unsigned bar, unsigned parity) {
    unsigned done;
    asm volatile(
        "{\n\t.reg .pred p;\n\t"
        "mbarrier.try_wait.parity.acquire.cta.shared::cta.b64 p, [%1], %2;\n\t"
        "selp.b32 %0, 1, 0, p;\n\t}"
        : "=r"(done) : "r"(bar), "r"(parity) : "memory");
    if (!done) {
        asm volatile(
            "{\n\t.reg .pred P1;\n\t"
            "WL_%=:\n\t"
            "mbarrier.try_wait.parity.acquire.cta.shared::cta.b64 P1, [%0], %1, 0x989680;\n\t"
            "@P1 bra.uni WD_%=;\n\t"
            "bra.uni WL_%=;\n\t"
            "WD_%=:\n\t}"
            :: "r"(bar), "r"(parity) : "memory");
    }
}

__global__ __launch_bounds__(THREADS)
void single_lr_gat_kernel(const float* __restrict__ r,
                          const float* __restrict__ lig,
                          const float* __restrict__ a,
                          const float* __restrict__ kl,
                          const float* __restrict__ bl,
                          const float* __restrict__ kr,
                          const float* __restrict__ br,
                          float* __restrict__ out) {
    __shared__ float4 lig_sh[2][1024];                 // 2 x 16KB
    __shared__ float4 a_sh4[2][16];                    // 2 x 256B
    __shared__ float4 red[2][8][16];                   // cross-warp partials, dbl-buffered
    __shared__ float  red0[2][8];
    __shared__ __align__(8) unsigned long long fullbar[2];

    const int tid  = threadIdx.x;
    const int lane = tid & 31;
    const int w    = tid >> 5;          // warp 0..7
    const int q    = lane & 15;         // quad along L
    const int mh   = lane >> 4;         // 4-row half within warp's 8 rows
    const int base = blockIdx.x * PAIRS_PER_CTA;

    const unsigned bar0 = smem_u32(&fullbar[0]);
    const unsigned bar1 = smem_u32(&fullbar[1]);
    const unsigned lig_s0 = smem_u32(&lig_sh[0][0]);
    const unsigned lig_s1 = smem_u32(&lig_sh[1][0]);
    const unsigned a_s0 = smem_u32(&a_sh4[0][0]);
    const unsigned a_s1 = smem_u32(&a_sh4[1][0]);

    if (tid == 0) {
        mbar_init(bar0, 1);
        mbar_init(bar1, 1);
    }
    __syncthreads();

    // Prologue: queue pairs 0 and 1.
    if (tid == 0) {
        mbar_expect_tx(bar0, TILE_BYTES + A_BYTES);
        bulk_g2s(lig_s0, lig + (size_t)(base + 0) * 4096, TILE_BYTES, bar0);
        bulk_g2s(a_s0,   a   + (size_t)(base + 0) * 64,   A_BYTES,   bar0);
        mbar_expect_tx(bar1, TILE_BYTES + A_BYTES);
        bulk_g2s(lig_s1, lig + (size_t)(base + 1) * 4096, TILE_BYTES, bar1);
        bulk_g2s(a_s1,   a   + (size_t)(base + 1) * 64,   A_BYTES,   bar1);
    }

    int phase0 = 0, phase1 = 0;

#pragma unroll 1
    for (int i = 0; i < PAIRS_PER_CTA; ++i) {
        const int b = i & 1;
        const unsigned bar = b ? bar1 : bar0;

        // Wait tile ready.
        if (b) { mbar_wait(bar1, phase1); phase1 ^= 1; }
        else   { mbar_wait(bar0, phase0); phase0 ^= 1; }

        // Compute partials: warp w, rows [8w + 4*mh, 8w + 4*mh + 4).
        const float4* __restrict__ buf = &lig_sh[b][0];
        const float*  __restrict__ av  = reinterpret_cast<const float*>(&a_sh4[b][0]);
        const int row0 = w * 8 + mh * 4;

        float4 s1 = make_float4(0.f, 0.f, 0.f, 0.f);
        float s0 = 0.f;
#pragma unroll
        for (int j = 0; j < 4; ++j) {
            const int row = row0 + j;
            const float4 v = buf[row * 16 + q];
            const float am = av[row];
            s1.x = fmaf(v.x, am, s1.x);
            s1.y = fmaf(v.y, am, s1.y);
            s1.z = fmaf(v.z, am, s1.z);
            s1.w = fmaf(v.w, am, s1.w);
            s0 += am;
        }
        // Combine mh halves within warp.
        s1.x += __shfl_xor_sync(0xFFFFFFFF, s1.x, 16);
        s1.y += __shfl_xor_sync(0xFFFFFFFF, s1.y, 16);
        s1.z += __shfl_xor_sync(0xFFFFFFFF, s1.z, 16);
        s1.w += __shfl_xor_sync(0xFFFFFFFF, s1.w, 16);
        s0   += __shfl_xor_sync(0xFFFFFFFF, s0,   16);

        if (lane < 16) red[b][w][q] = s1;
        if (lane == 0) red0[b][w] = s0;
        __syncthreads();   // red complete; all reads of lig_sh[b]/a_sh4[b] done

        // Buffer b is now free: queue pair i+2 into it.
        if (tid == 0 && i + 2 < PAIRS_PER_CTA) {
            const int p = base + i + 2;
            mbar_expect_tx(bar, TILE_BYTES + A_BYTES);
            bulk_g2s(b ? lig_s1 : lig_s0, lig + (size_t)p * 4096, TILE_BYTES, bar);
            bulk_g2s(b ? a_s1   : a_s0,   a   + (size_t)p * 64,   A_BYTES,   bar);
        }

        // Warp 0: final reduction + epilogue.
        if (w == 0 && lane < 16) {
            float4 t = red[b][0][q];
            float ts0 = red0[b][0];
#pragma unroll
            for (int k = 1; k < 8; ++k) {
                const float4 u = red[b][k][q];
                t.x += u.x; t.y += u.y; t.z += u.z; t.w += u.w;
                ts0 += red0[b][k];
            }
            const int pair = base + i;
            const float4 kl4 = reinterpret_cast<const float4*>(kl)[q];
            const float4 bl4 = reinterpret_cast<const float4*>(bl)[q];
            const float4 kr4 = reinterpret_cast<const float4*>(kr)[q];
            const float4 br4 = reinterpret_cast<const float4*>(br)[q];
            const float4 rv  = reinterpret_cast<const float4*>(r + (size_t)pair * 64)[q];

            float4 wv;
            wv.x = fmaf(kr4.x, rv.x, br4.x) * fmaf(kl4.x, t.x, bl4.x * ts0);
            wv.y = fmaf(kr4.y, rv.y, br4.y) * fmaf(kl4.y, t.y, bl4.y * ts0);
            wv.z = fmaf(kr4.z, rv.z, br4.z) * fmaf(kl4.z, t.z, bl4.z * ts0);
            wv.w = fmaf(kr4.w, rv.w, br4.w) * fmaf(kl4.w, t.w, bl4.w * ts0);

            float4 o;
            o.x = 1.f / (1.f + expf(-wv.x));
            o.y = 1.f / (1.f + expf(-wv.y));
            o.z = 1.f / (1.f + expf(-wv.z));
            o.w = 1.f / (1.f + expf(-wv.w));

            reinterpret_cast<float4*>(out + (size_t)pair * 64)[q] = o;
        }
        // No extra barrier needed: red[b] is next written at pair i+2, which is
        // ordered after warp 0's reads here via the __syncthreads at pair i+1.
    }
}

extern "C" void kernel_launch(void* const* d_in, const int* in_sizes, int n_in,
                              void* d_out, int out_size) {
    const float* r   = (const float*)d_in[0];
    const float* lig = (const float*)d_in[1];
    const float* a   = (const float*)d_in[2];
    const float* kl  = (const float*)d_in[3];
    const float* bl  = (const float*)d_in[4];
    const float* kr  = (const float*)d_in[5];
    const float* br  = (const float*)d_in[6];
    float* out = (float*)d_out;

    const int grid = NUM_PAIRS / PAIRS_PER_CTA;   // 8192/16 = 512
    single_lr_gat_kernel<<<grid, THREADS>>>(r, lig, a, kl, bl, kr, br, out);
}

// round 9
// speedup vs baseline: 1.1598x; 1.1391x over previous
#include <cuda_runtime.h>
#include <math.h>

// B=4, N=2048, M=64, L=64
// out[b,n,l] = sigmoid( (kr[l]*r[b,n,l]+br[l]) * (kl[l]*S1[l] + bl[l]*S0) )
//   S1[l] = sum_m lig[b,n,m,l]*a[b,n,m],  S0 = sum_m a[b,n,m]
//
// One warp per pair (best-known R6 structure), but the 16KB ligand tile is
// streamed via cp.async.cg (LDGSTS) into a warp-PRIVATE smem double buffer
// (8 chunks of 2KB, ring depth 2). In-flight DRAM bytes now live in smem, not
// registers: ~48 warps/SM x 2-4KB >> the ~10KB needed to cover DRAM latency.
// Zero block-level synchronization (only __syncwarp) — no lockstep coupling.
//
// lane = q + 16*mh: q = float4-quad along L, mh = row-half within a chunk.
// Per chunk (8 rows): each lane does 4 LDS.128 + fma, conflict-free.

#define THREADS 256
#define WARPS 8
#define NUM_PAIRS (4 * 2048)
#define CHUNK_FLOATS 512          // 8 rows x 64 = 2KB
#define NCHUNKS 8

__device__ __forceinline__ void cp16(unsigned dst, const void* src) {
    asm volatile("cp.async.cg.shared.global [%0], [%1], 16;" :: "r"(dst), "l"(src));
}
__device__ __forceinline__ void cp_commit() {
    asm volatile("cp.async.commit_group;" ::: "memory");
}
template <int N>
__device__ __forceinline__ void cp_wait() {
    asm volatile("cp.async.wait_group %0;" :: "n"(N) : "memory");
}

__global__ __launch_bounds__(THREADS, 6)
void single_lr_gat_kernel(const float* __restrict__ r,
                          const float* __restrict__ lig,
                          const float* __restrict__ a,
                          const float* __restrict__ kl,
                          const float* __restrict__ bl,
                          const float* __restrict__ kr,
                          const float* __restrict__ br,
                          float* __restrict__ out) {
    __shared__ float buf[WARPS][2][CHUNK_FLOATS];   // 8 x 2 x 2KB = 32KB
    __shared__ float a_sh[WARPS][64];               // 2KB

    const int tid  = threadIdx.x;
    const int lane = tid & 31;
    const int w    = tid >> 5;
    const int q    = lane & 15;     // quad along L
    const int mh   = lane >> 4;     // row-half within chunk
    const int pair = blockIdx.x * WARPS + w;

    // Stage this pair's a[64] into the warp's smem slot (coalesced, 256B).
    {
        const float* ap = a + (size_t)pair * 64;
        a_sh[w][lane]      = ap[lane];
        a_sh[w][lane + 32] = ap[lane + 32];
    }

    const char* gbase = (const char*)(lig + (size_t)pair * 4096);
    const unsigned sbase0 = (unsigned)__cvta_generic_to_shared(&buf[w][0][0]) + lane * 16;
    const unsigned sbase1 = (unsigned)__cvta_generic_to_shared(&buf[w][1][0]) + lane * 16;

    // Issue chunk c (2KB): 4 x 16B per lane, fully coalesced.
#define ISSUE(c)                                                          \
    do {                                                                  \
        const char* _s = gbase + (c) * 2048 + lane * 16;                  \
        const unsigned _d = ((c) & 1) ? sbase1 : sbase0;                  \
        cp16(_d,        _s);                                              \
        cp16(_d + 512,  _s + 512);                                        \
        cp16(_d + 1024, _s + 1024);                                       \
        cp16(_d + 1536, _s + 1536);                                       \
        cp_commit();                                                      \
    } while (0)

    ISSUE(0);
    ISSUE(1);
    __syncwarp();   // a_sh writes visible to all lanes

    float4 s1 = make_float4(0.f, 0.f, 0.f, 0.f);
    float s0 = 0.f;

#pragma unroll
    for (int t = 0; t < NCHUNKS; ++t) {
        if (t == NCHUNKS - 1) cp_wait<0>(); else cp_wait<1>();
        __syncwarp();   // make chunk t's smem visible to all lanes

        const float4* bp = reinterpret_cast<const float4*>(&buf[w][t & 1][0]);
        const float*  av = &a_sh[w][t * 8 + mh * 4];
#pragma unroll
        for (int j = 0; j < 4; ++j) {
            const float4 v = bp[(mh * 4 + j) * 16 + q];
            const float am = av[j];
            s1.x = fmaf(v.x, am, s1.x);
            s1.y = fmaf(v.y, am, s1.y);
            s1.z = fmaf(v.z, am, s1.z);
            s1.w = fmaf(v.w, am, s1.w);
            s0 += am;
        }
        __syncwarp();   // all lanes done reading buf before it is overwritten

        if (t < NCHUNKS - 2) ISSUE(t + 2);
    }
#undef ISSUE

    // Combine the two row-halves (lanes q and q+16 hold the same l's).
    s1.x += __shfl_xor_sync(0xFFFFFFFF, s1.x, 16);
    s1.y += __shfl_xor_sync(0xFFFFFFFF, s1.y, 16);
    s1.z += __shfl_xor_sync(0xFFFFFFFF, s1.z, 16);
    s1.w += __shfl_xor_sync(0xFFFFFFFF, s1.w, 16);
    s0   += __shfl_xor_sync(0xFFFFFFFF, s0,   16);

    if (lane < 16) {
        const float4 kl4 = reinterpret_cast<const float4*>(kl)[q];
        const float4 bl4 = reinterpret_cast<const float4*>(bl)[q];
        const float4 kr4 = reinterpret_cast<const float4*>(kr)[q];
        const float4 br4 = reinterpret_cast<const float4*>(br)[q];
        const float4 rv  = reinterpret_cast<const float4*>(r + (size_t)pair * 64)[q];

        float4 wv;
        wv.x = fmaf(kr4.x, rv.x, br4.x) * fmaf(kl4.x, s1.x, bl4.x * s0);
        wv.y = fmaf(kr4.y, rv.y, br4.y) * fmaf(kl4.y, s1.y, bl4.y * s0);
        wv.z = fmaf(kr4.z, rv.z, br4.z) * fmaf(kl4.z, s1.z, bl4.z * s0);
        wv.w = fmaf(kr4.w, rv.w, br4.w) * fmaf(kl4.w, s1.w, bl4.w * s0);

        float4 o;
        o.x = 1.f / (1.f + expf(-wv.x));
        o.y = 1.f / (1.f + expf(-wv.y));
        o.z = 1.f / (1.f + expf(-wv.z));
        o.w = 1.f / (1.f + expf(-wv.w));

        reinterpret_cast<float4*>(out + (size_t)pair * 64)[q] = o;
    }
}

extern "C" void kernel_launch(void* const* d_in, const int* in_sizes, int n_in,
                              void* d_out, int out_size) {
    const float* r   = (const float*)d_in[0];
    const float* lig = (const float*)d_in[1];
    const float* a   = (const float*)d_in[2];
    const float* kl  = (const float*)d_in[3];
    const float* bl  = (const float*)d_in[4];
    const float* kr  = (const float*)d_in[5];
    const float* br  = (const float*)d_in[6];
    float* out = (float*)d_out;

    const int grid = NUM_PAIRS / WARPS;   // 1024 blocks x 8 warps = 8192 pairs
    single_lr_gat_kernel<<<grid, THREADS>>>(r, lig, a, kl, bl, kr, br, out);
}

// round 10
// speedup vs baseline: 1.2597x; 1.0862x over previous
#include <cuda_runtime.h>
#include <math.h>

// B=4, N=2048, M=64, L=64
// out[b,n,l] = sigmoid( (kr[l]*r[b,n,l]+br[l]) * (kl[l]*S1[l] + bl[l]*S0) )
//   S1[l] = sum_m lig[b,n,m,l]*a[b,n,m],  S0 = sum_m a[b,n,m]
//
// L-SPLIT, fully independent warps: warp g handles pair g>>1, L-half g&1
// (32 features). 16384 warps total -> can fill all 64 warp slots/SM while
// resident (R6's 8192 warps capped occupancy at 81% and DRAM at 69%).
// Each warp reads 64B of every 128B ligand row; its partner warp reads the
// other 64B -> every DRAM line still consumed exactly once, traffic unchanged.
// No cross-warp communication at all (the block-level coupling that sank
// R7/R8). lane = q + 8*mh: q = float4-quad within the L-half, mh = one of
// four 16-m groups. Reduce via shfl_xor(16) then shfl_xor(8).

#define THREADS 256
#define WARPS 8
#define NUM_PAIRS (4 * 2048)
#define NUM_TASKS (NUM_PAIRS * 2)

__global__ __launch_bounds__(THREADS)
void single_lr_gat_kernel(const float* __restrict__ r,
                          const float* __restrict__ lig,
                          const float* __restrict__ a,
                          const float* __restrict__ kl,
                          const float* __restrict__ bl,
                          const float* __restrict__ kr,
                          const float* __restrict__ br,
                          float* __restrict__ out) {
    const int lane = threadIdx.x & 31;
    const int q    = lane & 7;          // quad within this warp's 32-feature half
    const int mh   = lane >> 3;         // 16-m group: m in [mh*16, mh*16+16)
    const int w    = threadIdx.x >> 5;
    const int g    = blockIdx.x * WARPS + w;   // task id
    const int pair = g >> 1;
    const int half = g & 1;             // L-half: features [half*32, half*32+32)

    __shared__ float a_sh[WARPS][64];

    // Per-warp private copy of a[pair,0:64] (partner warp loads its own copy;
    // the extra 2MB of a-reads is <1.5% of total traffic).
    {
        const float* ap = a + (size_t)pair * 64;
        a_sh[w][lane]      = ap[lane];
        a_sh[w][lane + 32] = ap[lane + 32];
    }
    __syncwarp();

    // lane reads float4 at row m = mh*16 + j, quad (half*8 + q).
    const float4* __restrict__ lig4 =
        reinterpret_cast<const float4*>(lig + (size_t)pair * 4096)
        + (mh * 16) * 16 + half * 8 + q;
    const float* __restrict__ arow = &a_sh[w][mh * 16];

    float4 s1 = make_float4(0.f, 0.f, 0.f, 0.f);
    float s0 = 0.f;

#pragma unroll 8
    for (int j = 0; j < 16; ++j) {
        const float4 v = __ldcs(&lig4[j * 16]);   // streaming: evict-first
        const float am = arow[j];
        s1.x = fmaf(v.x, am, s1.x);
        s1.y = fmaf(v.y, am, s1.y);
        s1.z = fmaf(v.z, am, s1.z);
        s1.w = fmaf(v.w, am, s1.w);
        s0 += am;
    }

    // Combine the four 16-m groups (lanes {q, q+8, q+16, q+24} share quad q).
    s1.x += __shfl_xor_sync(0xFFFFFFFF, s1.x, 16);
    s1.y += __shfl_xor_sync(0xFFFFFFFF, s1.y, 16);
    s1.z += __shfl_xor_sync(0xFFFFFFFF, s1.z, 16);
    s1.w += __shfl_xor_sync(0xFFFFFFFF, s1.w, 16);
    s0   += __shfl_xor_sync(0xFFFFFFFF, s0,   16);

    s1.x += __shfl_xor_sync(0xFFFFFFFF, s1.x, 8);
    s1.y += __shfl_xor_sync(0xFFFFFFFF, s1.y, 8);
    s1.z += __shfl_xor_sync(0xFFFFFFFF, s1.z, 8);
    s1.w += __shfl_xor_sync(0xFFFFFFFF, s1.w, 8);
    s0   += __shfl_xor_sync(0xFFFFFFFF, s0,   8);

    if (lane < 8) {
        const int qi = half * 8 + q;    // global quad index in [0,16)
        const float4 kl4 = reinterpret_cast<const float4*>(kl)[qi];
        const float4 bl4 = reinterpret_cast<const float4*>(bl)[qi];
        const float4 kr4 = reinterpret_cast<const float4*>(kr)[qi];
        const float4 br4 = reinterpret_cast<const float4*>(br)[qi];
        const float4 rv  = reinterpret_cast<const float4*>(r + (size_t)pair * 64)[qi];

        float4 wv;
        wv.x = fmaf(kr4.x, rv.x, br4.x) * fmaf(kl4.x, s1.x, bl4.x * s0);
        wv.y = fmaf(kr4.y, rv.y, br4.y) * fmaf(kl4.y, s1.y, bl4.y * s0);
        wv.z = fmaf(kr4.z, rv.z, br4.z) * fmaf(kl4.z, s1.z, bl4.z * s0);
        wv.w = fmaf(kr4.w, rv.w, br4.w) * fmaf(kl4.w, s1.w, bl4.w * s0);

        float4 o;
        o.x = 1.f / (1.f + expf(-wv.x));
        o.y = 1.f / (1.f + expf(-wv.y));
        o.z = 1.f / (1.f + expf(-wv.z));
        o.w = 1.f / (1.f + expf(-wv.w));

        reinterpret_cast<float4*>(out + (size_t)pair * 64)[qi] = o;
    }
}

extern "C" void kernel_launch(void* const* d_in, const int* in_sizes, int n_in,
                              void* d_out, int out_size) {
    const float* r   = (const float*)d_in[0];
    const float* lig = (const float*)d_in[1];
    const float* a   = (const float*)d_in[2];
    const float* kl  = (const float*)d_in[3];
    const float* bl  = (const float*)d_in[4];
    const float* kr  = (const float*)d_in[5];
    const float* br  = (const float*)d_in[6];
    float* out = (float*)d_out;

    const int grid = NUM_TASKS / WARPS;   // 16384/8 = 2048 blocks
    single_lr_gat_kernel<<<grid, THREADS>>>(r, lig, a, kl, bl, kr, br, out);
}